// round 1
// baseline (speedup 1.0000x reference)
#include <cuda_runtime.h>
#include <math.h>

// Problem constants
#define BB 64        // batch
#define TT 31        // timesteps (MAX_LEN-1)
#define EE 512       // embed dim
#define HH 1024      // hidden
#define GG 4096      // 4*hidden (gates)
#define VV 32000     // vocab

// Scratch (device globals; no cudaMalloc allowed)
__device__ float g_ctx[BB * HH];
__device__ float g_gbias[BB * GG];
__device__ float g_gx[(size_t)TT * BB * GG];     // GX + gbias folded, time-major
__device__ float g_h[2][BB * HH];
__device__ float g_c[BB * HH];
__device__ float g_hs[(size_t)TT * BB * HH];

// ---------------------------------------------------------------------------
// Zero h0 / c0 (deterministic across graph replays)
__global__ void k_init() {
    int i = blockIdx.x * blockDim.x + threadIdx.x;
    if (i < BB * HH) {
        g_h[0][i] = 0.f;
        g_c[i] = 0.f;
    }
}

// ---------------------------------------------------------------------------
// ctx[b,h] = sum_l features[b,l,h]   (attention weights are identically 1)
__global__ void k_ctx(const float* __restrict__ features) {
    int b = blockIdx.x;
    for (int h = threadIdx.x; h < HH; h += blockDim.x) {
        const float* p = features + (size_t)b * 64 * HH + h;
        float s = 0.f;
#pragma unroll 8
        for (int l = 0; l < 64; l++) s += p[(size_t)l * HH];
        g_ctx[b * HH + h] = s;
    }
}

// ---------------------------------------------------------------------------
// gbias[b,n] = b_ih[n] + b_hh[n] + sum_k ctx[b,k] * W_ih[n, 512+k]
// M=64, N=4096, K=1024.  Tile 64x64, 256 threads, 4x4 per thread.
__global__ __launch_bounds__(256) void k_gbias(const float* __restrict__ W_ih,
                                               const float* __restrict__ b_ih,
                                               const float* __restrict__ b_hh) {
    __shared__ float As[16][64];
    __shared__ float Bs[16][64];
    const int bn = blockIdx.x * 64;
    const int tx = threadIdx.x & 15, ty = threadIdx.x >> 4;
    const int lr = threadIdx.x >> 2;        // 0..63
    const int lk = (threadIdx.x & 3) * 4;   // 0,4,8,12
    float acc[4][4] = {};

    for (int k0 = 0; k0 < HH; k0 += 16) {
        float4 a = *(const float4*)(g_ctx + (size_t)lr * HH + k0 + lk);
        As[lk + 0][lr] = a.x; As[lk + 1][lr] = a.y; As[lk + 2][lr] = a.z; As[lk + 3][lr] = a.w;
        float4 w = *(const float4*)(W_ih + (size_t)(bn + lr) * 1536 + 512 + k0 + lk);
        Bs[lk + 0][lr] = w.x; Bs[lk + 1][lr] = w.y; Bs[lk + 2][lr] = w.z; Bs[lk + 3][lr] = w.w;
        __syncthreads();
#pragma unroll
        for (int kk = 0; kk < 16; kk++) {
            float ra[4], rb[4];
#pragma unroll
            for (int i = 0; i < 4; i++) ra[i] = As[kk][ty * 4 + i];
#pragma unroll
            for (int j = 0; j < 4; j++) rb[j] = Bs[kk][tx * 4 + j];
#pragma unroll
            for (int i = 0; i < 4; i++)
#pragma unroll
                for (int j = 0; j < 4; j++) acc[i][j] += ra[i] * rb[j];
        }
        __syncthreads();
    }
#pragma unroll
    for (int i = 0; i < 4; i++) {
        int m = ty * 4 + i;
#pragma unroll
        for (int j = 0; j < 4; j++) {
            int n = bn + tx * 4 + j;
            g_gbias[m * GG + n] = acc[i][j] + b_ih[n] + b_hh[n];
        }
    }
}

// ---------------------------------------------------------------------------
// gx[(t*64+b), n] = gbias[b,n] + sum_k embed[captions[b,t], k] * W_ih[n, k]
// M=1984 (tiled 64 => blockIdx.y = t), N=4096 (tiled 64), K=512.
__global__ __launch_bounds__(256) void k_gx(const float* __restrict__ embed,
                                            const int* __restrict__ captions,
                                            const float* __restrict__ W_ih) {
    __shared__ float As[16][64];
    __shared__ float Bs[16][64];
    __shared__ int sIdx[64];
    const int t = blockIdx.y;           // 0..30
    const int bn = blockIdx.x * 64;
    if (threadIdx.x < 64) sIdx[threadIdx.x] = captions[threadIdx.x * 32 + t];
    __syncthreads();

    const int tx = threadIdx.x & 15, ty = threadIdx.x >> 4;
    const int lr = threadIdx.x >> 2;
    const int lk = (threadIdx.x & 3) * 4;
    float acc[4][4] = {};

    for (int k0 = 0; k0 < EE; k0 += 16) {
        float4 a = *(const float4*)(embed + (size_t)sIdx[lr] * EE + k0 + lk);
        As[lk + 0][lr] = a.x; As[lk + 1][lr] = a.y; As[lk + 2][lr] = a.z; As[lk + 3][lr] = a.w;
        float4 w = *(const float4*)(W_ih + (size_t)(bn + lr) * 1536 + k0 + lk);
        Bs[lk + 0][lr] = w.x; Bs[lk + 1][lr] = w.y; Bs[lk + 2][lr] = w.z; Bs[lk + 3][lr] = w.w;
        __syncthreads();
#pragma unroll
        for (int kk = 0; kk < 16; kk++) {
            float ra[4], rb[4];
#pragma unroll
            for (int i = 0; i < 4; i++) ra[i] = As[kk][ty * 4 + i];
#pragma unroll
            for (int j = 0; j < 4; j++) rb[j] = Bs[kk][tx * 4 + j];
#pragma unroll
            for (int i = 0; i < 4; i++)
#pragma unroll
                for (int j = 0; j < 4; j++) acc[i][j] += ra[i] * rb[j];
        }
        __syncthreads();
    }
#pragma unroll
    for (int i = 0; i < 4; i++) {
        int b = ty * 4 + i;
#pragma unroll
        for (int j = 0; j < 4; j++) {
            int n = bn + tx * 4 + j;
            g_gx[((size_t)t * 64 + b) * GG + n] = acc[i][j] + g_gbias[b * GG + n];
        }
    }
}

// ---------------------------------------------------------------------------
// One recurrent step. Block handles 8 hidden units (all 4 gates, all 64 batches):
// 64x32 output tile, K=1024. Then does the LSTM pointwise locally.
__global__ __launch_bounds__(256) void k_step(const float* __restrict__ W_hh, int t) {
    __shared__ float As[16][64];
    __shared__ float Bs[16][32];
    __shared__ float sg[64][33];
    const int jj0 = blockIdx.x * 8;                 // 128 blocks * 8 = 1024 hidden
    const float* __restrict__ h_in = g_h[t & 1];
    float* __restrict__ h_out = g_h[(t + 1) & 1];

    const int tx = threadIdx.x & 15, ty = threadIdx.x >> 4;
    const int lr = threadIdx.x >> 2;                // As: 64 rows x 16k, 4 floats each
    const int lk = (threadIdx.x & 3) * 4;
    const int brow = threadIdx.x >> 3;              // Bs: 32 rows x 16k, 2 floats each
    const int bk = (threadIdx.x & 7) * 2;
    const int grow = (brow >> 3) * HH + jj0 + (brow & 7);   // W_hh row for tile col brow

    float acc[4][2] = {};
    for (int k0 = 0; k0 < HH; k0 += 16) {
        float4 a = *(const float4*)(h_in + (size_t)lr * HH + k0 + lk);
        As[lk + 0][lr] = a.x; As[lk + 1][lr] = a.y; As[lk + 2][lr] = a.z; As[lk + 3][lr] = a.w;
        float2 w = *(const float2*)(W_hh + (size_t)grow * HH + k0 + bk);
        Bs[bk + 0][brow] = w.x; Bs[bk + 1][brow] = w.y;
        __syncthreads();
#pragma unroll
        for (int kk = 0; kk < 16; kk++) {
            float ra[4], rb[2];
#pragma unroll
            for (int i = 0; i < 4; i++) ra[i] = As[kk][ty * 4 + i];
#pragma unroll
            for (int j = 0; j < 2; j++) rb[j] = Bs[kk][tx * 2 + j];
#pragma unroll
            for (int i = 0; i < 4; i++)
#pragma unroll
                for (int j = 0; j < 2; j++) acc[i][j] += ra[i] * rb[j];
        }
        __syncthreads();
    }

    // gates tile -> smem, with precomputed (GX + gbias) added
    const float* __restrict__ gx = g_gx + (size_t)t * 64 * GG;
#pragma unroll
    for (int i = 0; i < 4; i++) {
        int b = ty * 4 + i;
#pragma unroll
        for (int j = 0; j < 2; j++) {
            int n = tx * 2 + j;                          // n = gate*8 + hh
            int gidx = (n >> 3) * HH + jj0 + (n & 7);    // global gate index
            sg[b][n] = acc[i][j] + gx[(size_t)b * GG + gidx];
        }
    }
    __syncthreads();

    // LSTM pointwise: 64 batches x 8 hidden
    for (int u = threadIdx.x; u < 512; u += 256) {
        int b = u >> 3, hh = u & 7;
        float gi = sg[b][hh];
        float gf = sg[b][8 + hh];
        float gg = sg[b][16 + hh];
        float go = sg[b][24 + hh];
        int ci = b * HH + jj0 + hh;
        float cOld = g_c[ci];
        float si = 1.f / (1.f + expf(-gi));
        float sf = 1.f / (1.f + expf(-gf));
        float so = 1.f / (1.f + expf(-go));
        float cN = sf * cOld + si * tanhf(gg);
        float hN = so * tanhf(cN);
        g_c[ci] = cN;
        h_out[ci] = hN;
        g_hs[((size_t)t * 64 + b) * HH + jj0 + hh] = hN;
    }
}

// ---------------------------------------------------------------------------
// logits[m, v] = sum_k hs[m,k] * lin_W[v,k] + lin_b[v]
// M=1984 (tile 64), N=32000 (tile 128), K=1024. 256 threads, 4x8 per thread.
__global__ __launch_bounds__(256) void k_logits(const float* __restrict__ lin_W,
                                                const float* __restrict__ lin_b,
                                                float* __restrict__ out) {
    __shared__ float As[16][64];
    __shared__ float Bs[16][128];
    const int bm = blockIdx.y * 64;
    const int bn = blockIdx.x * 128;
    const int tx = threadIdx.x & 15, ty = threadIdx.x >> 4;
    const int lr = threadIdx.x >> 2;              // As loader: 64x16
    const int lk = (threadIdx.x & 3) * 4;
    const int br = threadIdx.x >> 1;              // Bs loader: 128x16, 8 floats/thread
    const int bk8 = (threadIdx.x & 1) * 8;

    float acc[4][8] = {};
    for (int k0 = 0; k0 < HH; k0 += 16) {
        float4 a = *(const float4*)(g_hs + (size_t)(bm + lr) * HH + k0 + lk);
        As[lk + 0][lr] = a.x; As[lk + 1][lr] = a.y; As[lk + 2][lr] = a.z; As[lk + 3][lr] = a.w;
        const float* wp = lin_W + (size_t)(bn + br) * HH + k0 + bk8;
        float4 w0 = *(const float4*)(wp);
        float4 w1 = *(const float4*)(wp + 4);
        Bs[bk8 + 0][br] = w0.x; Bs[bk8 + 1][br] = w0.y; Bs[bk8 + 2][br] = w0.z; Bs[bk8 + 3][br] = w0.w;
        Bs[bk8 + 4][br] = w1.x; Bs[bk8 + 5][br] = w1.y; Bs[bk8 + 6][br] = w1.z; Bs[bk8 + 7][br] = w1.w;
        __syncthreads();
#pragma unroll
        for (int kk = 0; kk < 16; kk++) {
            float ra[4], rb[8];
#pragma unroll
            for (int i = 0; i < 4; i++) ra[i] = As[kk][ty * 4 + i];
#pragma unroll
            for (int j = 0; j < 8; j++) rb[j] = Bs[kk][tx * 8 + j];
#pragma unroll
            for (int i = 0; i < 4; i++)
#pragma unroll
                for (int j = 0; j < 8; j++) acc[i][j] += ra[i] * rb[j];
        }
        __syncthreads();
    }
#pragma unroll
    for (int i = 0; i < 4; i++) {
        int m = bm + ty * 4 + i;
#pragma unroll
        for (int j = 0; j < 8; j++) {
            int n = bn + tx * 8 + j;
            out[(size_t)m * VV + n] = acc[i][j] + lin_b[n];
        }
    }
}

// ---------------------------------------------------------------------------
extern "C" void kernel_launch(void* const* d_in, const int* in_sizes, int n_in,
                              void* d_out, int out_size) {
    const float* features = (const float*)d_in[0];
    const int*   captions = (const int*)d_in[1];
    // d_in[2] lengths: full lengths, no-op under pack_padded with sorted full lengths
    const float* embed    = (const float*)d_in[3];
    const float* W_ih     = (const float*)d_in[4];
    const float* W_hh     = (const float*)d_in[5];
    const float* b_ih     = (const float*)d_in[6];
    const float* b_hh     = (const float*)d_in[7];
    // d_in[8] attn_W, d_in[9] attn_b: dead code (softmax over singleton dim == 1)
    const float* lin_W    = (const float*)d_in[10];
    const float* lin_b    = (const float*)d_in[11];
    float* out = (float*)d_out;

    k_init<<<(BB * HH + 255) / 256, 256>>>();
    k_ctx<<<BB, 256>>>(features);
    k_gbias<<<GG / 64, 256>>>(W_ih, b_ih, b_hh);
    k_gx<<<dim3(GG / 64, TT), 256>>>(embed, captions, W_ih);
    for (int t = 0; t < TT; t++)
        k_step<<<HH / 8, 256>>>(W_hh, t);
    k_logits<<<dim3(VV / 128, TT), 256>>>(lin_W, lin_b, out);
}

// round 3
// speedup vs baseline: 2.4430x; 2.4430x over previous
#include <cuda_runtime.h>
#include <cuda_bf16.h>
#include <math.h>

#define BB 64
#define TT 31
#define EE 512
#define HH 1024
#define GG 4096
#define VV 32000

__device__ float g_ctx[BB * HH];
__device__ float g_gbias[BB * GG];
__device__ float g_emb[(size_t)TT * BB * EE];
__device__ float g_gx[(size_t)TT * BB * GG];
__device__ float g_h[2][BB * HH];
__device__ float g_c[BB * HH];
__device__ float g_hs[(size_t)TT * BB * HH];

// ---------------------------------------------------------------------------
// Split fp32 pair into packed bf16 hi / lo (Ootomo bf16x3 decomposition)
__device__ __forceinline__ void cvt2(float x, float y, unsigned& hi, unsigned& lo) {
    __nv_bfloat16 hx = __float2bfloat16(x), hy = __float2bfloat16(y);
    float rx = x - __bfloat162float(hx);
    float ry = y - __bfloat162float(hy);
    __nv_bfloat162 H = __halves2bfloat162(hx, hy);
    __nv_bfloat162 L = __floats2bfloat162_rn(rx, ry);
    hi = *(unsigned*)&H;
    lo = *(unsigned*)&L;
}
__device__ __forceinline__ void mma_bf16(float c[4], const unsigned a[4], const unsigned b[2]) {
    asm("mma.sync.aligned.m16n8k16.row.col.f32.bf16.bf16.f32 "
        "{%0,%1,%2,%3},{%4,%5,%6,%7},{%8,%9},{%0,%1,%2,%3};"
        : "+f"(c[0]), "+f"(c[1]), "+f"(c[2]), "+f"(c[3])
        : "r"(a[0]), "r"(a[1]), "r"(a[2]), "r"(a[3]), "r"(b[0]), "r"(b[1]));
}

// ---------------------------------------------------------------------------
__global__ void k_init() {
    int i = blockIdx.x * blockDim.x + threadIdx.x;
    if (i < BB * HH) { g_h[0][i] = 0.f; g_c[i] = 0.f; }
}

__global__ void k_ctx(const float* __restrict__ features) {
    int b = blockIdx.x;
    for (int h = threadIdx.x; h < HH; h += blockDim.x) {
        const float* p = features + (size_t)b * 64 * HH + h;
        float s = 0.f;
#pragma unroll 8
        for (int l = 0; l < 64; l++) s += p[(size_t)l * HH];
        g_ctx[b * HH + h] = s;
    }
}

__global__ void k_emb(const float* __restrict__ embed, const int* __restrict__ captions) {
    int v = blockIdx.x * blockDim.x + threadIdx.x;
    int m = v >> 7;
    int e4 = (v & 127) << 2;
    int t = m / 64, b = m % 64;
    int cap = captions[b * 32 + t];
    *(float4*)(g_emb + (size_t)m * EE + e4) =
        *(const float4*)(embed + (size_t)cap * EE + e4);
}

// ---------------------------------------------------------------------------
// bf16x3 GEMM: C[m,n] = sum_k A[m,k]*B[n,k] + epilogue.
// BM=64, BN=128, BK=16 (8 packed pairs), 256 threads, warp tile 32x32.
// Smem rows stride 12 (8 payload pairs): addr = 12*g + tig is a mod-32
// permutation -> conflict-free fragment loads.
template<int MODE>
__global__ __launch_bounds__(256) void k_mm(
    const float* __restrict__ A, int lda,
    const float* __restrict__ B, int ldb,
    float* __restrict__ C, int ldc, int K,
    const float* __restrict__ bias1, const float* __restrict__ bias2,
    const float* __restrict__ addM)
{
    __shared__ unsigned AsH[2][64][12], AsL[2][64][12];
    __shared__ unsigned BsH[2][128][12], BsL[2][128][12];
    const int tid = threadIdx.x;
    const int wid = tid >> 5, lane = tid & 31, g = lane >> 2, tig = lane & 3;
    const int wm = (wid & 1) * 32, wn = (wid >> 1) * 32;
    const int bm = blockIdx.y * 64, bn = blockIdx.x * 128;

    const int ar = tid >> 2;
    const int ac = (tid & 3) * 4;       // k offset of this thread's float4
    const int pc = ac >> 1;             // pair index base (0,2,4,6)
    const float* Arow = A + (size_t)(bm + ar) * lda + ac;
    const float* Brow0 = B + (size_t)(bn + ar) * ldb + ac;
    const float* Brow1 = B + (size_t)(bn + ar + 64) * ldb + ac;

    float acc[2][4][4] = {};
    float4 aR, bR0, bR1;

    aR = *(const float4*)(Arow);
    bR0 = *(const float4*)(Brow0);
    bR1 = *(const float4*)(Brow1);
    {
        unsigned h0, l0, h1, l1;
        cvt2(aR.x, aR.y, h0, l0); cvt2(aR.z, aR.w, h1, l1);
        AsH[0][ar][pc] = h0; AsH[0][ar][pc + 1] = h1;
        AsL[0][ar][pc] = l0; AsL[0][ar][pc + 1] = l1;
        cvt2(bR0.x, bR0.y, h0, l0); cvt2(bR0.z, bR0.w, h1, l1);
        BsH[0][ar][pc] = h0; BsH[0][ar][pc + 1] = h1;
        BsL[0][ar][pc] = l0; BsL[0][ar][pc + 1] = l1;
        cvt2(bR1.x, bR1.y, h0, l0); cvt2(bR1.z, bR1.w, h1, l1);
        BsH[0][ar + 64][pc] = h0; BsH[0][ar + 64][pc + 1] = h1;
        BsL[0][ar + 64][pc] = l0; BsL[0][ar + 64][pc + 1] = l1;
    }
    __syncthreads();

    const int KT = K >> 4;
    for (int kt = 0; kt < KT; kt++) {
        const int cur = kt & 1;
        if (kt + 1 < KT) {
            aR = *(const float4*)(Arow + (kt + 1) * 16);
            bR0 = *(const float4*)(Brow0 + (kt + 1) * 16);
            bR1 = *(const float4*)(Brow1 + (kt + 1) * 16);
        }
        {
            unsigned afH[2][4], afL[2][4], bfH[4][2], bfL[4][2];
#pragma unroll
            for (int mt = 0; mt < 2; mt++) {
                int r = wm + mt * 16 + g;
                afH[mt][0] = AsH[cur][r][tig];     afH[mt][1] = AsH[cur][r + 8][tig];
                afH[mt][2] = AsH[cur][r][tig + 4]; afH[mt][3] = AsH[cur][r + 8][tig + 4];
                afL[mt][0] = AsL[cur][r][tig];     afL[mt][1] = AsL[cur][r + 8][tig];
                afL[mt][2] = AsL[cur][r][tig + 4]; afL[mt][3] = AsL[cur][r + 8][tig + 4];
            }
#pragma unroll
            for (int nt = 0; nt < 4; nt++) {
                int n = wn + nt * 8 + g;
                bfH[nt][0] = BsH[cur][n][tig]; bfH[nt][1] = BsH[cur][n][tig + 4];
                bfL[nt][0] = BsL[cur][n][tig]; bfL[nt][1] = BsL[cur][n][tig + 4];
            }
#pragma unroll
            for (int mt = 0; mt < 2; mt++)
#pragma unroll
                for (int nt = 0; nt < 4; nt++) {
                    mma_bf16(acc[mt][nt], afL[mt], bfH[nt]);
                    mma_bf16(acc[mt][nt], afH[mt], bfL[nt]);
                    mma_bf16(acc[mt][nt], afH[mt], bfH[nt]);
                }
        }
        if (kt + 1 < KT) {
            const int nxt = cur ^ 1;
            unsigned h0, l0, h1, l1;
            cvt2(aR.x, aR.y, h0, l0); cvt2(aR.z, aR.w, h1, l1);
            AsH[nxt][ar][pc] = h0; AsH[nxt][ar][pc + 1] = h1;
            AsL[nxt][ar][pc] = l0; AsL[nxt][ar][pc + 1] = l1;
            cvt2(bR0.x, bR0.y, h0, l0); cvt2(bR0.z, bR0.w, h1, l1);
            BsH[nxt][ar][pc] = h0; BsH[nxt][ar][pc + 1] = h1;
            BsL[nxt][ar][pc] = l0; BsL[nxt][ar][pc + 1] = l1;
            cvt2(bR1.x, bR1.y, h0, l0); cvt2(bR1.z, bR1.w, h1, l1);
            BsH[nxt][ar + 64][pc] = h0; BsH[nxt][ar + 64][pc + 1] = h1;
            BsL[nxt][ar + 64][pc] = l0; BsL[nxt][ar + 64][pc + 1] = l1;
            __syncthreads();
        }
    }

#pragma unroll
    for (int mt = 0; mt < 2; mt++) {
#pragma unroll
        for (int nt = 0; nt < 4; nt++) {
#pragma unroll
            for (int q = 0; q < 4; q++) {
                int r = bm + wm + mt * 16 + g + ((q >> 1) * 8);
                int n = bn + wn + nt * 8 + 2 * tig + (q & 1);
                float v = acc[mt][nt][q];
                if (MODE == 0) v += bias1[n] + bias2[n];
                if (MODE == 1) v += addM[(size_t)(r & 63) * GG + n];
                if (MODE == 2) v += bias1[n];
                C[(size_t)r * ldc + n] = v;
            }
        }
    }
}

// ---------------------------------------------------------------------------
// Recurrent step: gates(64x32) = h_in @ W_hh(permuted cols), fused LSTM.
// grid = 128 blocks (8 hidden x 4 gates per block).
__global__ __launch_bounds__(256) void k_step(const float* __restrict__ W_hh, int t) {
    __shared__ unsigned AsH[2][64][12], AsL[2][64][12];
    __shared__ unsigned BsH[2][32][12], BsL[2][32][12];
    __shared__ float sg[64][33];
    const int tid = threadIdx.x;
    const int wid = tid >> 5, lane = tid & 31, g = lane >> 2, tig = lane & 3;
    const int wm = (wid & 1) * 32, wn = (wid >> 1) * 8;
    const int jj0 = blockIdx.x * 8;
    const float* __restrict__ h_in = g_h[t & 1];
    float* __restrict__ h_out = g_h[(t + 1) & 1];

    const int ar = tid >> 2;
    const int ac = (tid & 3) * 4;
    const int pc = ac >> 1;
    const float* Arow = h_in + (size_t)ar * HH + ac;
    const float* Brow = nullptr;
    if (tid < 128) {
        int br = tid >> 2;
        int wrow = (br >> 3) * HH + jj0 + (br & 7);
        Brow = W_hh + (size_t)wrow * HH + ac;
    }

    float acc[2][4] = {};
    float4 aR, bR;
    aR = *(const float4*)(Arow);
    if (tid < 128) bR = *(const float4*)(Brow);
    {
        unsigned h0, l0, h1, l1;
        cvt2(aR.x, aR.y, h0, l0); cvt2(aR.z, aR.w, h1, l1);
        AsH[0][ar][pc] = h0; AsH[0][ar][pc + 1] = h1;
        AsL[0][ar][pc] = l0; AsL[0][ar][pc + 1] = l1;
        if (tid < 128) {
            int br = tid >> 2;
            cvt2(bR.x, bR.y, h0, l0); cvt2(bR.z, bR.w, h1, l1);
            BsH[0][br][pc] = h0; BsH[0][br][pc + 1] = h1;
            BsL[0][br][pc] = l0; BsL[0][br][pc + 1] = l1;
        }
    }
    __syncthreads();

    const int KT = HH >> 4;
    for (int kt = 0; kt < KT; kt++) {
        const int cur = kt & 1;
        if (kt + 1 < KT) {
            aR = *(const float4*)(Arow + (kt + 1) * 16);
            if (tid < 128) bR = *(const float4*)(Brow + (kt + 1) * 16);
        }
        {
            unsigned afH[2][4], afL[2][4], bfH[2], bfL[2];
#pragma unroll
            for (int mt = 0; mt < 2; mt++) {
                int r = wm + mt * 16 + g;
                afH[mt][0] = AsH[cur][r][tig];     afH[mt][1] = AsH[cur][r + 8][tig];
                afH[mt][2] = AsH[cur][r][tig + 4]; afH[mt][3] = AsH[cur][r + 8][tig + 4];
                afL[mt][0] = AsL[cur][r][tig];     afL[mt][1] = AsL[cur][r + 8][tig];
                afL[mt][2] = AsL[cur][r][tig + 4]; afL[mt][3] = AsL[cur][r + 8][tig + 4];
            }
            int n = wn + g;
            bfH[0] = BsH[cur][n][tig]; bfH[1] = BsH[cur][n][tig + 4];
            bfL[0] = BsL[cur][n][tig]; bfL[1] = BsL[cur][n][tig + 4];
#pragma unroll
            for (int mt = 0; mt < 2; mt++) {
                mma_bf16(acc[mt], afL[mt], bfH);
                mma_bf16(acc[mt], afH[mt], bfL);
                mma_bf16(acc[mt], afH[mt], bfH);
            }
        }
        if (kt + 1 < KT) {
            const int nxt = cur ^ 1;
            unsigned h0, l0, h1, l1;
            cvt2(aR.x, aR.y, h0, l0); cvt2(aR.z, aR.w, h1, l1);
            AsH[nxt][ar][pc] = h0; AsH[nxt][ar][pc + 1] = h1;
            AsL[nxt][ar][pc] = l0; AsL[nxt][ar][pc + 1] = l1;
            if (tid < 128) {
                int br = tid >> 2;
                cvt2(bR.x, bR.y, h0, l0); cvt2(bR.z, bR.w, h1, l1);
                BsH[nxt][br][pc] = h0; BsH[nxt][br][pc + 1] = h1;
                BsL[nxt][br][pc] = l0; BsL[nxt][br][pc + 1] = l1;
            }
            __syncthreads();
        }
    }

#pragma unroll
    for (int mt = 0; mt < 2; mt++)
#pragma unroll
        for (int q = 0; q < 4; q++) {
            int r = wm + mt * 16 + g + ((q >> 1) * 8);
            int j = wn + 2 * tig + (q & 1);
            sg[r][j] = acc[mt][q];
        }
    __syncthreads();

    const float* __restrict__ gx = g_gx + (size_t)t * 64 * GG;
    for (int u = tid; u < 512; u += 256) {
        int b = u >> 3, hh = u & 7;
        size_t gbase = (size_t)b * GG + jj0 + hh;
        float gi = sg[b][0 * 8 + hh] + gx[gbase];
        float gf = sg[b][1 * 8 + hh] + gx[gbase + HH];
        float gg = sg[b][2 * 8 + hh] + gx[gbase + 2 * HH];
        float go = sg[b][3 * 8 + hh] + gx[gbase + 3 * HH];
        int ci = b * HH + jj0 + hh;
        float cOld = g_c[ci];
        float si = 1.f / (1.f + expf(-gi));
        float sf = 1.f / (1.f + expf(-gf));
        float so = 1.f / (1.f + expf(-go));
        float cN = sf * cOld + si * tanhf(gg);
        float hN = so * tanhf(cN);
        g_c[ci] = cN;
        h_out[ci] = hN;
        g_hs[((size_t)t * 64 + b) * HH + jj0 + hh] = hN;
    }
}

// ---------------------------------------------------------------------------
extern "C" void kernel_launch(void* const* d_in, const int* in_sizes, int n_in,
                              void* d_out, int out_size) {
    const float* features = (const float*)d_in[0];
    const int*   captions = (const int*)d_in[1];
    const float* embed    = (const float*)d_in[3];
    const float* W_ih     = (const float*)d_in[4];
    const float* W_hh     = (const float*)d_in[5];
    const float* b_ih     = (const float*)d_in[6];
    const float* b_hh     = (const float*)d_in[7];
    const float* lin_W    = (const float*)d_in[10];
    const float* lin_b    = (const float*)d_in[11];
    float* out = (float*)d_out;

    float* p_ctx;   cudaGetSymbolAddress((void**)&p_ctx, g_ctx);
    float* p_gbias; cudaGetSymbolAddress((void**)&p_gbias, g_gbias);
    float* p_emb;   cudaGetSymbolAddress((void**)&p_emb, g_emb);
    float* p_gx;    cudaGetSymbolAddress((void**)&p_gx, g_gx);
    float* p_hs;    cudaGetSymbolAddress((void**)&p_hs, g_hs);

    k_init<<<(BB * HH + 255) / 256, 256>>>();
    k_ctx<<<BB, 256>>>(features);
    k_emb<<<(TT * BB * EE / 4 + 255) / 256, 256>>>(embed, captions);
    k_mm<0><<<dim3(GG / 128, 1), 256>>>(p_ctx, HH, W_ih + 512, 1536, p_gbias, GG, HH,
                                        b_ih, b_hh, nullptr);
    k_mm<1><<<dim3(GG / 128, TT), 256>>>(p_emb, EE, W_ih, 1536, p_gx, GG, EE,
                                         nullptr, nullptr, p_gbias);
    for (int t = 0; t < TT; t++)
        k_step<<<128, 256>>>(W_hh, t);
    k_mm<2><<<dim3(VV / 128, TT), 256>>>(p_hs, HH, lin_W, HH, out, VV, HH,
                                         lin_b, nullptr, nullptr);
}

// round 4
// speedup vs baseline: 2.5195x; 1.0313x over previous
#include <cuda_runtime.h>
#include <cuda_bf16.h>
#include <math.h>

#define BB 64
#define TT 31
#define EE 512
#define HH 1024
#define GG 4096
#define VV 32000
typedef __nv_bfloat16 bf;

// Pre-split bf16 hi/lo operand storage (device globals; no cudaMalloc allowed)
__device__ __align__(16) bf g_linWH[(size_t)VV * HH], g_linWL[(size_t)VV * HH];
__device__ __align__(16) bf g_WihH[(size_t)GG * 1536], g_WihL[(size_t)GG * 1536];
__device__ __align__(16) bf g_WhhH[(size_t)GG * HH], g_WhhL[(size_t)GG * HH];
__device__ __align__(16) bf g_ctxH[BB * HH], g_ctxL[BB * HH];
__device__ __align__(16) bf g_embH[(size_t)TT * BB * EE], g_embL[(size_t)TT * BB * EE];
__device__ __align__(16) bf g_hsH[(size_t)TT * BB * HH], g_hsL[(size_t)TT * BB * HH];
__device__ __align__(16) bf g_h0H[BB * HH], g_h0L[BB * HH];
__device__ float g_gbias[BB * GG];
__device__ float g_gx[(size_t)TT * BB * GG];
__device__ float g_c[BB * HH];

// ---------------------------------------------------------------------------
#define CP16(dst, src) asm volatile("cp.async.ca.shared.global [%0], [%1], 16;" :: "r"(dst), "l"(src) : "memory")
#define CP_COMMIT() asm volatile("cp.async.commit_group;" ::: "memory")
#define CP_WAIT0() asm volatile("cp.async.wait_group 0;" ::: "memory")
__device__ __forceinline__ unsigned s2u(const void* p) {
    return (unsigned)__cvta_generic_to_shared(p);
}
__device__ __forceinline__ void mma_bf16(float c[4], const unsigned a[4], const unsigned b[2]) {
    asm("mma.sync.aligned.m16n8k16.row.col.f32.bf16.bf16.f32 "
        "{%0,%1,%2,%3},{%4,%5,%6,%7},{%8,%9},{%0,%1,%2,%3};"
        : "+f"(c[0]), "+f"(c[1]), "+f"(c[2]), "+f"(c[3])
        : "r"(a[0]), "r"(a[1]), "r"(a[2]), "r"(a[3]), "r"(b[0]), "r"(b[1]));
}
__device__ __forceinline__ void split2(float x, float y, unsigned& hi, unsigned& lo) {
    bf hx = __float2bfloat16(x), hy = __float2bfloat16(y);
    __nv_bfloat162 H = __halves2bfloat162(hx, hy);
    __nv_bfloat162 L = __halves2bfloat162(__float2bfloat16(x - __bfloat162float(hx)),
                                          __float2bfloat16(y - __bfloat162float(hy)));
    hi = *(unsigned*)&H;
    lo = *(unsigned*)&L;
}

// ---------------------------------------------------------------------------
__global__ void k_init() {
    int i = blockIdx.x * blockDim.x + threadIdx.x;
    if (i < BB * HH) {
        g_h0H[i] = __float2bfloat16(0.f);
        g_h0L[i] = __float2bfloat16(0.f);
        g_c[i] = 0.f;
    }
}

// fp32 -> bf16 hi/lo split, 4 elements per thread
__global__ void k_conv(const float4* __restrict__ S, uint2* __restrict__ H,
                       uint2* __restrict__ L, int n4) {
    int i = blockIdx.x * blockDim.x + threadIdx.x;
    if (i >= n4) return;
    float4 v = S[i];
    uint2 h, l;
    split2(v.x, v.y, h.x, l.x);
    split2(v.z, v.w, h.y, l.y);
    H[i] = h;
    L[i] = l;
}

// ctx[b,h] = sum_l features[b,l,h] (attention weights identically 1), split to hi/lo
__global__ void k_ctx(const float* __restrict__ features) {
    int b = blockIdx.x;
    for (int h = threadIdx.x; h < HH; h += blockDim.x) {
        const float* p = features + (size_t)b * 64 * HH + h;
        float s = 0.f;
#pragma unroll 8
        for (int l = 0; l < 64; l++) s += p[(size_t)l * HH];
        bf hi = __float2bfloat16(s);
        g_ctxH[b * HH + h] = hi;
        g_ctxL[b * HH + h] = __float2bfloat16(s - __bfloat162float(hi));
    }
}

// gathered embeddings (time-major), split to hi/lo
__global__ void k_emb(const float* __restrict__ embed, const int* __restrict__ captions) {
    int v = blockIdx.x * blockDim.x + threadIdx.x;
    int m = v >> 7;
    int e4 = (v & 127) << 2;
    int t = m / 64, b = m % 64;
    int cap = captions[b * 32 + t];
    float4 val = *(const float4*)(embed + (size_t)cap * EE + e4);
    uint2 h, l;
    split2(val.x, val.y, h.x, l.x);
    split2(val.z, val.w, h.y, l.y);
    ((uint2*)g_embH)[((size_t)m * EE + e4) >> 2] = h;
    ((uint2*)g_embL)[((size_t)m * EE + e4) >> 2] = l;
}

// ---------------------------------------------------------------------------
// bf16x3 GEMM, pre-split operands, cp.async double-buffered.
// BM=64, BN=128, BK=16, 256 threads, warp tile 32x32.
template<int MODE>
__global__ __launch_bounds__(256) void k_mm(
    const bf* __restrict__ AH, const bf* __restrict__ AL, int lda,
    const bf* __restrict__ BH, const bf* __restrict__ BL, int ldb,
    float* __restrict__ C, int ldc, int K,
    const float* __restrict__ bias1, const float* __restrict__ bias2,
    const float* __restrict__ addM)
{
    __shared__ unsigned AsH[2][64][12], AsL[2][64][12];
    __shared__ unsigned BsH[2][128][12], BsL[2][128][12];
    const int tid = threadIdx.x;
    const int wid = tid >> 5, lane = tid & 31, g = lane >> 2, tig = lane & 3;
    const int wm = (wid & 1) * 32, wn = (wid >> 1) * 32;
    const int bm = blockIdx.y * 64, bn = blockIdx.x * 128;

    // A copy task: 64 rows x {H,L} x 2 chunks = 256
    const int arow = tid >> 2, asel = (tid >> 1) & 1, achk = tid & 1;
    const bf* aSrc = (asel ? AL : AH) + (size_t)(bm + arow) * lda + achk * 8;
    unsigned aD[2] = { s2u(&(asel ? AsL : AsH)[0][arow][achk * 4]),
                       s2u(&(asel ? AsL : AsH)[1][arow][achk * 4]) };
    // B copy tasks: 128 rows x {H,L} x 2 chunks = 512 -> 2 per thread
    const int b0r = tid >> 2, b0s = (tid >> 1) & 1, b0c = tid & 1;
    const int id1 = tid + 256;
    const int b1r = id1 >> 2, b1s = (id1 >> 1) & 1, b1c = id1 & 1;
    const bf* bSrc0 = (b0s ? BL : BH) + (size_t)(bn + b0r) * ldb + b0c * 8;
    const bf* bSrc1 = (b1s ? BL : BH) + (size_t)(bn + b1r) * ldb + b1c * 8;
    unsigned b0D[2] = { s2u(&(b0s ? BsL : BsH)[0][b0r][b0c * 4]),
                        s2u(&(b0s ? BsL : BsH)[1][b0r][b0c * 4]) };
    unsigned b1D[2] = { s2u(&(b1s ? BsL : BsH)[0][b1r][b1c * 4]),
                        s2u(&(b1s ? BsL : BsH)[1][b1r][b1c * 4]) };

    float acc[2][4][4] = {};

    CP16(aD[0], aSrc); CP16(b0D[0], bSrc0); CP16(b1D[0], bSrc1); CP_COMMIT();

    const int KT = K >> 4;
    for (int kt = 0; kt < KT; kt++) {
        const int cur = kt & 1, nxt = cur ^ 1;
        CP_WAIT0();
        __syncthreads();
        if (kt + 1 < KT) {
            CP16(aD[nxt], aSrc + (kt + 1) * 16);
            CP16(b0D[nxt], bSrc0 + (kt + 1) * 16);
            CP16(b1D[nxt], bSrc1 + (kt + 1) * 16);
            CP_COMMIT();
        }
        unsigned afH[2][4], afL[2][4], bfH[4][2], bfL[4][2];
#pragma unroll
        for (int mt = 0; mt < 2; mt++) {
            int r = wm + mt * 16 + g;
            afH[mt][0] = AsH[cur][r][tig];     afH[mt][1] = AsH[cur][r + 8][tig];
            afH[mt][2] = AsH[cur][r][tig + 4]; afH[mt][3] = AsH[cur][r + 8][tig + 4];
            afL[mt][0] = AsL[cur][r][tig];     afL[mt][1] = AsL[cur][r + 8][tig];
            afL[mt][2] = AsL[cur][r][tig + 4]; afL[mt][3] = AsL[cur][r + 8][tig + 4];
        }
#pragma unroll
        for (int nt = 0; nt < 4; nt++) {
            int n = wn + nt * 8 + g;
            bfH[nt][0] = BsH[cur][n][tig]; bfH[nt][1] = BsH[cur][n][tig + 4];
            bfL[nt][0] = BsL[cur][n][tig]; bfL[nt][1] = BsL[cur][n][tig + 4];
        }
#pragma unroll
        for (int mt = 0; mt < 2; mt++)
#pragma unroll
            for (int nt = 0; nt < 4; nt++) {
                mma_bf16(acc[mt][nt], afL[mt], bfH[nt]);
                mma_bf16(acc[mt][nt], afH[mt], bfL[nt]);
                mma_bf16(acc[mt][nt], afH[mt], bfH[nt]);
            }
    }

#pragma unroll
    for (int mt = 0; mt < 2; mt++) {
#pragma unroll
        for (int nt = 0; nt < 4; nt++) {
            int r0 = bm + wm + mt * 16 + g, r1 = r0 + 8;
            int n0 = bn + wn + nt * 8 + 2 * tig;
            float2 v01 = make_float2(acc[mt][nt][0], acc[mt][nt][1]);
            float2 v23 = make_float2(acc[mt][nt][2], acc[mt][nt][3]);
            if (MODE == 0) {
                float2 x = *(const float2*)(bias1 + n0);
                float2 y = *(const float2*)(bias2 + n0);
                v01.x += x.x + y.x; v01.y += x.y + y.y;
                v23.x += x.x + y.x; v23.y += x.y + y.y;
            }
            if (MODE == 1) {
                float2 x = *(const float2*)(addM + (size_t)(r0 & 63) * GG + n0);
                float2 y = *(const float2*)(addM + (size_t)(r1 & 63) * GG + n0);
                v01.x += x.x; v01.y += x.y;
                v23.x += y.x; v23.y += y.y;
            }
            if (MODE == 2) {
                float2 x = *(const float2*)(bias1 + n0);
                v01.x += x.x; v01.y += x.y;
                v23.x += x.x; v23.y += x.y;
            }
            *(float2*)(C + (size_t)r0 * ldc + n0) = v01;
            *(float2*)(C + (size_t)r1 * ldc + n0) = v23;
        }
    }
}

// ---------------------------------------------------------------------------
// Recurrent step: gates(64x32) = h(t-1) @ W_hh(permuted cols), fused LSTM.
__global__ __launch_bounds__(256) void k_step(const bf* __restrict__ AH,
                                              const bf* __restrict__ AL, int t) {
    __shared__ unsigned AsH[2][64][12], AsL[2][64][12];
    __shared__ unsigned BsH[2][32][12], BsL[2][32][12];
    __shared__ float sg[64][33];
    const int tid = threadIdx.x;
    const int wid = tid >> 5, lane = tid & 31, g = lane >> 2, tig = lane & 3;
    const int wm = (wid & 1) * 32, wn = (wid >> 1) * 8;
    const int jj0 = blockIdx.x * 8;

    const int arow = tid >> 2, asel = (tid >> 1) & 1, achk = tid & 1;
    const bf* aSrc = (asel ? AL : AH) + (size_t)arow * HH + achk * 8;
    unsigned aD[2] = { s2u(&(asel ? AsL : AsH)[0][arow][achk * 4]),
                       s2u(&(asel ? AsL : AsH)[1][arow][achk * 4]) };
    const bf* bSrc = nullptr;
    unsigned bD[2] = {0, 0};
    if (tid < 128) {
        int br = tid >> 2, bs = (tid >> 1) & 1, bc = tid & 1;
        int wrow = (br >> 3) * HH + jj0 + (br & 7);
        bSrc = (bs ? g_WhhL : g_WhhH) + (size_t)wrow * HH + bc * 8;
        bD[0] = s2u(&(bs ? BsL : BsH)[0][br][bc * 4]);
        bD[1] = s2u(&(bs ? BsL : BsH)[1][br][bc * 4]);
    }

    float acc[2][4] = {};
    CP16(aD[0], aSrc);
    if (tid < 128) CP16(bD[0], bSrc);
    CP_COMMIT();

    const int KT = HH >> 4;
    for (int kt = 0; kt < KT; kt++) {
        const int cur = kt & 1, nxt = cur ^ 1;
        CP_WAIT0();
        __syncthreads();
        if (kt + 1 < KT) {
            CP16(aD[nxt], aSrc + (kt + 1) * 16);
            if (tid < 128) CP16(bD[nxt], bSrc + (kt + 1) * 16);
            CP_COMMIT();
        }
        unsigned afH[2][4], afL[2][4], bfH[2], bfL[2];
#pragma unroll
        for (int mt = 0; mt < 2; mt++) {
            int r = wm + mt * 16 + g;
            afH[mt][0] = AsH[cur][r][tig];     afH[mt][1] = AsH[cur][r + 8][tig];
            afH[mt][2] = AsH[cur][r][tig + 4]; afH[mt][3] = AsH[cur][r + 8][tig + 4];
            afL[mt][0] = AsL[cur][r][tig];     afL[mt][1] = AsL[cur][r + 8][tig];
            afL[mt][2] = AsL[cur][r][tig + 4]; afL[mt][3] = AsL[cur][r + 8][tig + 4];
        }
        int n = wn + g;
        bfH[0] = BsH[cur][n][tig]; bfH[1] = BsH[cur][n][tig + 4];
        bfL[0] = BsL[cur][n][tig]; bfL[1] = BsL[cur][n][tig + 4];
#pragma unroll
        for (int mt = 0; mt < 2; mt++) {
            mma_bf16(acc[mt], afL[mt], bfH);
            mma_bf16(acc[mt], afH[mt], bfL);
            mma_bf16(acc[mt], afH[mt], bfH);
        }
    }

#pragma unroll
    for (int mt = 0; mt < 2; mt++)
#pragma unroll
        for (int q = 0; q < 4; q++) {
            int r = wm + mt * 16 + g + ((q >> 1) * 8);
            int j = wn + 2 * tig + (q & 1);
            sg[r][j] = acc[mt][q];
        }
    __syncthreads();

    const float* __restrict__ gx = g_gx + (size_t)t * 64 * GG;
    for (int u = tid; u < 512; u += 256) {
        int b = u >> 3, hh = u & 7;
        size_t gbase = (size_t)b * GG + jj0 + hh;
        float gi = sg[b][0 * 8 + hh] + gx[gbase];
        float gf = sg[b][1 * 8 + hh] + gx[gbase + HH];
        float gg = sg[b][2 * 8 + hh] + gx[gbase + 2 * HH];
        float go = sg[b][3 * 8 + hh] + gx[gbase + 3 * HH];
        int ci = b * HH + jj0 + hh;
        float cOld = g_c[ci];
        float si = 1.f / (1.f + expf(-gi));
        float sf = 1.f / (1.f + expf(-gf));
        float so = 1.f / (1.f + expf(-go));
        float cN = sf * cOld + si * tanhf(gg);
        float hN = so * tanhf(cN);
        g_c[ci] = cN;
        size_t hidx = ((size_t)t * 64 + b) * HH + jj0 + hh;
        bf hb = __float2bfloat16(hN);
        g_hsH[hidx] = hb;
        g_hsL[hidx] = __float2bfloat16(hN - __bfloat162float(hb));
    }
}

// ---------------------------------------------------------------------------
extern "C" void kernel_launch(void* const* d_in, const int* in_sizes, int n_in,
                              void* d_out, int out_size) {
    const float* features = (const float*)d_in[0];
    const int*   captions = (const int*)d_in[1];
    const float* embed    = (const float*)d_in[3];
    const float* W_ih     = (const float*)d_in[4];
    const float* W_hh     = (const float*)d_in[5];
    const float* b_ih     = (const float*)d_in[6];
    const float* b_hh     = (const float*)d_in[7];
    const float* lin_W    = (const float*)d_in[10];
    const float* lin_b    = (const float*)d_in[11];
    float* out = (float*)d_out;

    bf *p_linWH, *p_linWL, *p_WihH, *p_WihL, *p_WhhH, *p_WhhL;
    bf *p_ctxH, *p_ctxL, *p_embH, *p_embL, *p_hsH, *p_hsL, *p_h0H, *p_h0L;
    float *p_gbias, *p_gx;
    cudaGetSymbolAddress((void**)&p_linWH, g_linWH);
    cudaGetSymbolAddress((void**)&p_linWL, g_linWL);
    cudaGetSymbolAddress((void**)&p_WihH, g_WihH);
    cudaGetSymbolAddress((void**)&p_WihL, g_WihL);
    cudaGetSymbolAddress((void**)&p_WhhH, g_WhhH);
    cudaGetSymbolAddress((void**)&p_WhhL, g_WhhL);
    cudaGetSymbolAddress((void**)&p_ctxH, g_ctxH);
    cudaGetSymbolAddress((void**)&p_ctxL, g_ctxL);
    cudaGetSymbolAddress((void**)&p_embH, g_embH);
    cudaGetSymbolAddress((void**)&p_embL, g_embL);
    cudaGetSymbolAddress((void**)&p_hsH, g_hsH);
    cudaGetSymbolAddress((void**)&p_hsL, g_hsL);
    cudaGetSymbolAddress((void**)&p_h0H, g_h0H);
    cudaGetSymbolAddress((void**)&p_h0L, g_h0L);
    cudaGetSymbolAddress((void**)&p_gbias, g_gbias);
    cudaGetSymbolAddress((void**)&p_gx, g_gx);

    k_init<<<(BB * HH + 255) / 256, 256>>>();
    int n4;
    n4 = VV * HH / 4;
    k_conv<<<(n4 + 255) / 256, 256>>>((const float4*)lin_W, (uint2*)p_linWH, (uint2*)p_linWL, n4);
    n4 = GG * 1536 / 4;
    k_conv<<<(n4 + 255) / 256, 256>>>((const float4*)W_ih, (uint2*)p_WihH, (uint2*)p_WihL, n4);
    n4 = GG * HH / 4;
    k_conv<<<(n4 + 255) / 256, 256>>>((const float4*)W_hh, (uint2*)p_WhhH, (uint2*)p_WhhL, n4);
    k_ctx<<<BB, 256>>>(features);
    k_emb<<<(TT * BB * EE / 4 + 255) / 256, 256>>>(embed, captions);
    // gbias = ctx @ W_ih[:,512:]^T + b_ih + b_hh
    k_mm<0><<<dim3(GG / 128, 1), 256>>>(p_ctxH, p_ctxL, HH,
                                        p_WihH + 512, p_WihL + 512, 1536,
                                        p_gbias, GG, HH, b_ih, b_hh, nullptr);
    // gx = emb @ W_ih[:,:512]^T + gbias
    k_mm<1><<<dim3(GG / 128, TT), 256>>>(p_embH, p_embL, EE,
                                         p_WihH, p_WihL, 1536,
                                         p_gx, GG, EE, nullptr, nullptr, p_gbias);
    for (int t = 0; t < TT; t++) {
        const bf* AH = t ? p_hsH + (size_t)(t - 1) * BB * HH : p_h0H;
        const bf* AL = t ? p_hsL + (size_t)(t - 1) * BB * HH : p_h0L;
        k_step<<<128, 256>>>(AH, AL, t);
    }
    // logits = hs @ lin_W^T + lin_b
    k_mm<2><<<dim3(VV / 128, TT), 256>>>(p_hsH, p_hsL, HH,
                                         p_linWH, p_linWL, HH,
                                         out, VV, HH, lin_b, nullptr, nullptr);
}